// round 14
// baseline (speedup 1.0000x reference)
#include <cuda_runtime.h>
#include <math.h>

#define BATCH 16
#define SEQ 1024
#define IN_DIM 310
#define E 64
#define NH 8
#define HD 8
#define ROWS (BATCH*SEQ)          // 16384
#define WIN 5
#define NKEYS 342                 // #{j < 1024 : j%3==0}
#define SCALE 0.35355339059327373f  // 1/sqrt(8)

typedef unsigned long long ull;

// ---------------- f32x2 packed helpers ----------------
__device__ __forceinline__ ull pk2(float lo, float hi) {
    ull r; asm("mov.b64 %0,{%1,%2};" : "=l"(r) : "f"(lo), "f"(hi)); return r;
}
__device__ __forceinline__ void upk2(ull v, float& lo, float& hi) {
    asm("mov.b64 {%0,%1},%2;" : "=f"(lo), "=f"(hi) : "l"(v));
}
__device__ __forceinline__ ull ffma2(ull a, ull b, ull c) {
    ull d; asm("fma.rn.f32x2 %0,%1,%2,%3;" : "=l"(d) : "l"(a), "l"(b), "l"(c)); return d;
}
__device__ __forceinline__ ull fmul2(ull a, ull b) {
    ull d; asm("mul.rn.f32x2 %0,%1,%2;" : "=l"(d) : "l"(a), "l"(b)); return d;
}

// ---------------- scratch ----------------
__device__ float g_xp[ROWS*E];
__device__ float g_q[2][BATCH*NH*SEQ*HD];
__device__ float g_k[2][BATCH*NH*SEQ*HD];
__device__ float g_v[2][BATCH*NH*SEQ*HD];
__device__ float g_o[2][ROWS*E];
__device__ float g_M[2][E*E];
__device__ float g_cb[E];
__device__ float g_scores[ROWS];
__device__ float g_fused[ROWS*E];

// ======== split GEMM: 64x64 tile, TWO 128-thread groups, microtile 8x4 each ========
struct HalfSmem {
    float As[16][68];
    float Ws[16][68];
};
struct SplitSmem {
    HalfSmem h[2];
    float part[64][68];
};

__device__ __forceinline__ void gemm64_grp(
    HalfSmem& sm,
    const float* __restrict__ A, int lda, int row0,
    const float* __restrict__ W, int ldw,
    int kb, int ke, int nchunk,
    ull (&acc)[4][4], int t)
{
    int tc = t & 15, tr = t >> 4;   // tr 0..7
    for (int ci = 0; ci < nchunk; ci++) {
        int k0 = kb + ci * 16;
        #pragma unroll
        for (int p = 0; p < 8; p++) {      // A: 64x16
            int i = t + p * 128;
            int kk = i & 15, r = i >> 4;
            int k = k0 + kk;
            sm.As[kk][r] = (k < ke) ? A[(size_t)(row0 + r) * lda + k] : 0.f;
        }
        #pragma unroll
        for (int p = 0; p < 8; p++) {      // W: 64x16
            int i = t + p * 128;
            int kk = i & 15, c = i >> 4;
            int k = k0 + kk;
            sm.Ws[kk][c] = (k < ke) ? W[(size_t)c * ldw + k] : 0.f;
        }
        __syncthreads();
        #pragma unroll
        for (int kk = 0; kk < 16; kk++) {
            ulonglong2 a01 = *(const ulonglong2*)&sm.As[kk][8*tr];
            ulonglong2 a23 = *(const ulonglong2*)&sm.As[kk][8*tr + 4];
            float4 wv = *(const float4*)&sm.Ws[kk][4*tc];
            ull ap[4] = {a01.x, a01.y, a23.x, a23.y};
            ull w2[4] = {pk2(wv.x, wv.x), pk2(wv.y, wv.y), pk2(wv.z, wv.z), pk2(wv.w, wv.w)};
            #pragma unroll
            for (int p = 0; p < 4; p++)
                #pragma unroll
                for (int j = 0; j < 4; j++)
                    acc[p][j] = ffma2(ap[p], w2[j], acc[p][j]);
        }
        __syncthreads();
    }
}

__device__ __forceinline__ void split_reduce_store(
    SplitSmem& sm, ull (&acc)[4][4], int grp, int t,
    const float* __restrict__ bias, float* __restrict__ outbase, int row0)
{
    int tc = t & 15, tr = t >> 4;
    if (grp == 1) {
        #pragma unroll
        for (int p = 0; p < 4; p++) {
            float lo[4], hi[4];
            #pragma unroll
            for (int j = 0; j < 4; j++) upk2(acc[p][j], lo[j], hi[j]);
            int r = 8*tr + 2*p;
            *(float4*)&sm.part[r][4*tc]   = make_float4(lo[0], lo[1], lo[2], lo[3]);
            *(float4*)&sm.part[r+1][4*tc] = make_float4(hi[0], hi[1], hi[2], hi[3]);
        }
    }
    __syncthreads();
    if (grp == 0) {
        float4 bv = *(const float4*)&bias[4*tc];
        #pragma unroll
        for (int p = 0; p < 4; p++) {
            float lo[4], hi[4];
            #pragma unroll
            for (int j = 0; j < 4; j++) upk2(acc[p][j], lo[j], hi[j]);
            int r = 8*tr + 2*p;
            float4 p0 = *(const float4*)&sm.part[r][4*tc];
            float4 p1 = *(const float4*)&sm.part[r+1][4*tc];
            float4 v0 = {lo[0]+p0.x+bv.x, lo[1]+p0.y+bv.y, lo[2]+p0.z+bv.z, lo[3]+p0.w+bv.w};
            float4 v1 = {hi[0]+p1.x+bv.x, hi[1]+p1.y+bv.y, hi[2]+p1.z+bv.z, hi[3]+p1.w+bv.w};
            *(float4*)&outbase[(size_t)(row0 + r)*E + 4*tc] = v0;
            *(float4*)&outbase[(size_t)(row0 + r + 1)*E + 4*tc] = v1;
        }
    }
}

// ---------------- combine_w (blocks 0..15) + proj (blocks 16..271) ----------------
__global__ __launch_bounds__(256) void combine_proj_kernel(
    const float* __restrict__ x,
    const float* __restrict__ pw, const float* __restrict__ pb,
    const float* __restrict__ fw, const float* __restrict__ fb,
    const float* __restrict__ low, const float* __restrict__ lob,
    const float* __restrict__ gow, const float* __restrict__ gob)
{
    __shared__ SplitSmem sm;
    int tid = threadIdx.x;
    int blk = blockIdx.x;
    if (blk < 16) {
        int idx = blk * 256 + tid;             // 0..4095
        int e = idx >> 6, f = idx & 63;
        float a = 0.f, b = 0.f;
        #pragma unroll 4
        for (int g = 0; g < E; g++) {
            a = fmaf(fw[e*2*E + g],     low[g*E + f], a);
            b = fmaf(fw[e*2*E + E + g], gow[g*E + f], b);
        }
        g_M[0][idx] = a;
        g_M[1][idx] = b;
        if (idx < E) {
            float c = fb[idx];
            for (int g = 0; g < E; g++) {
                c = fmaf(fw[idx*2*E + g], lob[g], c);
                c = fmaf(fw[idx*2*E + E + g], gob[g], c);
            }
            g_cb[idx] = c;
        }
        return;
    }
    int row0 = (blk - 16) * 64;
    int grp = tid >> 7, t = tid & 127;
    int kb = grp ? 160 : 0;
    int ke = grp ? IN_DIM : 160;
    ull acc[4][4] = {};
    gemm64_grp(sm.h[grp], x, IN_DIM, row0, pw, IN_DIM, kb, ke, 10, acc, t);
    split_reduce_store(sm, acc, grp, t, pb, g_xp, row0);
}

// ---------------- QKV: 64 rows x 192 cols per block, 256 threads (R4 config) ----------------
__global__ __launch_bounds__(256) void qkv_kernel(const float* __restrict__ loc_w,
                           const float* __restrict__ loc_b,
                           const float* __restrict__ glb_w,
                           const float* __restrict__ glb_b) {
    __shared__ float As[16][68];
    __shared__ float Ws[16][196];
    int tid = threadIdx.x;
    int row0 = blockIdx.x * 64;
    int attn = blockIdx.y;
    const float* w    = attn ? glb_w : loc_w;
    const float* bias = attn ? glb_b : loc_b;
    int tc = tid & 15, tr = tid >> 4;
    ull acc[2][12] = {};
    for (int k0 = 0; k0 < E; k0 += 16) {
        #pragma unroll
        for (int p = 0; p < 4; p++) {          // A: 64x16
            int i = tid + p * 256;
            int kk = i & 15, r = i >> 4;
            As[kk][r] = g_xp[(size_t)(row0 + r) * E + k0 + kk];
        }
        #pragma unroll
        for (int p = 0; p < 12; p++) {         // W: 192x16
            int i = tid + p * 256;
            int kk = i & 15, c = i >> 4;
            Ws[kk][c] = w[(size_t)c * E + k0 + kk];
        }
        __syncthreads();
        #pragma unroll
        for (int kk = 0; kk < 16; kk++) {
            ulonglong2 a01 = *(const ulonglong2*)&As[kk][4*tr];
            #pragma unroll
            for (int cg = 0; cg < 3; cg++) {
                float4 wv = *(const float4*)&Ws[kk][64*cg + 4*tc];
                ull w2[4] = {pk2(wv.x, wv.x), pk2(wv.y, wv.y), pk2(wv.z, wv.z), pk2(wv.w, wv.w)};
                #pragma unroll
                for (int j = 0; j < 4; j++) {
                    acc[0][cg*4+j] = ffma2(a01.x, w2[j], acc[0][cg*4+j]);
                    acc[1][cg*4+j] = ffma2(a01.y, w2[j], acc[1][cg*4+j]);
                }
            }
        }
        __syncthreads();
    }
    int c = 4*tc;
    int h = c >> 3, dd = c & 7;
    #pragma unroll
    for (int cg = 0; cg < 3; cg++) {
        float* outp = (cg == 0) ? g_q[attn] : (cg == 1) ? g_k[attn] : g_v[attn];
        float4 bv = *(const float4*)&bias[cg*64 + c];
        #pragma unroll
        for (int p = 0; p < 2; p++) {
            float lo[4], hi[4];
            #pragma unroll
            for (int j = 0; j < 4; j++) upk2(acc[p][cg*4+j], lo[j], hi[j]);
            int row = row0 + 4*tr + 2*p;
            int b0 = row >> 10, s0 = row & 1023;
            int b1 = (row+1) >> 10, s1 = (row+1) & 1023;
            float4 v0 = {lo[0]+bv.x, lo[1]+bv.y, lo[2]+bv.z, lo[3]+bv.w};
            float4 v1 = {hi[0]+bv.x, hi[1]+bv.y, hi[2]+bv.z, hi[3]+bv.w};
            *(float4*)&outp[(((size_t)(b0*NH + h))*SEQ + s0)*HD + dd] = v0;
            *(float4*)&outp[(((size_t)(b1*NH + h))*SEQ + s1)*HD + dd] = v1;
        }
    }
}

// ---------------- both attentions in one launch (R4/R10 config) ----------------
__global__ __launch_bounds__(256) void attn_kernel() {
    __shared__ union {
        struct { float Ks[NKEYS][8]; float Vs[NKEYS][8]; } sp;
        struct { ull K2[4][272]; ull V2[4][272]; } loc;
    } u;
    int blk = blockIdx.x;
    int tid = threadIdx.x;
    if (blk < 512) {
        // ---- local path ----
        int bh = blk >> 2;
        int chunk0 = (blk & 3) * 256;
        const float* kb = g_k[0] + (size_t)bh * SEQ * HD;
        const float* vb = g_v[0] + (size_t)bh * SEQ * HD;
        for (int i = tid; i < 266*4; i += 256) {
            int dp = i & 3, r = i >> 2;
            int row = chunk0 - 5 + r;
            ull kv = 0, vv = 0;
            if (row >= 0 && row < SEQ) {
                kv = *(const ull*)(kb + (size_t)row*HD + 2*dp);
                vv = *(const ull*)(vb + (size_t)row*HD + 2*dp);
            }
            u.loc.K2[dp][r] = kv;
            u.loc.V2[dp][r] = vv;
        }
        __syncthreads();
        int s = chunk0 + tid;
        const ull* qp = (const ull*)(g_q[0] + ((size_t)bh * SEQ + s) * HD);
        ull q0 = qp[0], q1 = qp[1], q2 = qp[2], q3 = qp[3];
        float l = 0.f;
        ull acc[4] = {0,0,0,0};
        int j0 = s - WIN;
        #pragma unroll
        for (int jj = 0; jj < 2*WIN+1; jj++) {
            int r = tid + jj;
            ull d2 = ffma2(q0, u.loc.K2[0][r],
                     ffma2(q1, u.loc.K2[1][r],
                     ffma2(q2, u.loc.K2[2][r],
                     fmul2(q3, u.loc.K2[3][r]))));
            float dl, dh; upk2(d2, dl, dh);
            unsigned jg = (unsigned)(j0 + jj);
            float p = (jg < SEQ) ? __expf((dl + dh) * SCALE) : 0.f;
            l += p;
            ull pp = pk2(p, p);
            acc[0] = ffma2(pp, u.loc.V2[0][r], acc[0]);
            acc[1] = ffma2(pp, u.loc.V2[1][r], acc[1]);
            acc[2] = ffma2(pp, u.loc.V2[2][r], acc[2]);
            acc[3] = ffma2(pp, u.loc.V2[3][r], acc[3]);
        }
        float inv = 1.f / l;
        float oo[8];
        upk2(acc[0], oo[0], oo[1]); upk2(acc[1], oo[2], oo[3]);
        upk2(acc[2], oo[4], oo[5]); upk2(acc[3], oo[6], oo[7]);
        int b = bh >> 3, h = bh & 7;
        float* op = g_o[0] + ((size_t)(b*SEQ + s))*E + h*HD;
        float4 o0 = {oo[0]*inv, oo[1]*inv, oo[2]*inv, oo[3]*inv};
        float4 o1 = {oo[4]*inv, oo[5]*inv, oo[6]*inv, oo[7]*inv};
        *(float4*)op = o0;
        *(float4*)(op + 4) = o1;
    } else {
        // ---- sparse path ----
        int bb = blk - 512;
        int bh = bb >> 2;
        int s  = (bb & 3) * 256 + tid;
        const float* kb = g_k[1] + (size_t)bh * SEQ * HD;
        const float* vb = g_v[1] + (size_t)bh * SEQ * HD;
        for (int i = tid; i < NKEYS*8; i += 256) {
            int kk = i >> 3, dd = i & 7;
            u.sp.Ks[kk][dd] = kb[kk*24 + dd];
            u.sp.Vs[kk][dd] = vb[kk*24 + dd];
        }
        __syncthreads();
        const ull* qp = (const ull*)(g_q[1] + ((size_t)bh * SEQ + s) * HD);
        ull q0 = qp[0], q1 = qp[1], q2 = qp[2], q3 = qp[3];
        float l = 0.f;
        ull acc[4] = {0,0,0,0};
        #pragma unroll 2
        for (int kk = 0; kk < NKEYS; kk++) {
            const ull* kp = (const ull*)&u.sp.Ks[kk][0];
            ull d2 = ffma2(q0, kp[0], ffma2(q1, kp[1], ffma2(q2, kp[2], fmul2(q3, kp[3]))));
            float dl, dh; upk2(d2, dl, dh);
            float p = __expf((dl + dh) * SCALE);
            l += p;
            ull pp = pk2(p, p);
            const ull* vp = (const ull*)&u.sp.Vs[kk][0];
            acc[0] = ffma2(pp, vp[0], acc[0]);
            acc[1] = ffma2(pp, vp[1], acc[1]);
            acc[2] = ffma2(pp, vp[2], acc[2]);
            acc[3] = ffma2(pp, vp[3], acc[3]);
        }
        if (s % 3) {
            const ull* kp = (const ull*)(kb + (size_t)s * HD);
            ull d2 = ffma2(q0, kp[0], ffma2(q1, kp[1], ffma2(q2, kp[2], fmul2(q3, kp[3]))));
            float dl, dh; upk2(d2, dl, dh);
            float p = __expf((dl + dh) * SCALE);
            l += p;
            ull pp = pk2(p, p);
            const ull* vp = (const ull*)(vb + (size_t)s * HD);
            acc[0] = ffma2(pp, vp[0], acc[0]);
            acc[1] = ffma2(pp, vp[1], acc[1]);
            acc[2] = ffma2(pp, vp[2], acc[2]);
            acc[3] = ffma2(pp, vp[3], acc[3]);
        }
        float inv = 1.f / l;
        float oo[8];
        upk2(acc[0], oo[0], oo[1]); upk2(acc[1], oo[2], oo[3]);
        upk2(acc[2], oo[4], oo[5]); upk2(acc[3], oo[6], oo[7]);
        int b = bh >> 3, h = bh & 7;
        float* op = g_o[1] + ((size_t)(b*SEQ + s))*E + h*HD;
        float4 o0 = {oo[0]*inv, oo[1]*inv, oo[2]*inv, oo[3]*inv};
        float4 o1 = {oo[4]*inv, oo[5]*inv, oo[6]*inv, oo[7]*inv};
        *(float4*)op = o0;
        *(float4*)(op + 4) = o1;
    }
}

// ---------------- fused: split across the two source GEMMs (R10 config) ----------------
__global__ __launch_bounds__(256) void fused_kernel() {
    __shared__ SplitSmem sm;
    int tid = threadIdx.x;
    int row0 = blockIdx.x * 64;
    int grp = tid >> 7, t = tid & 127;
    const float* A = grp ? g_o[1] : g_o[0];
    const float* W = grp ? g_M[1] : g_M[0];
    ull acc[4][4] = {};
    gemm64_grp(sm.h[grp], A, E, row0, W, E, 0, E, 4, acc, t);
    split_reduce_store(sm, acc, grp, t, g_cb, g_fused, row0);
}

// ---------------- pooling logits: GEMM-style, broadcast LDS, k-pair ffma2 ----------------
__global__ __launch_bounds__(256) void pool_score_kernel(
    const float* __restrict__ w1, const float* __restrict__ b1,
    const float* __restrict__ w2, const float* __restrict__ b2)
{
    __shared__ __align__(16) float fs[64][68];   // fused tile, row-major
    __shared__ __align__(16) float w1s[32][68];  // w1 row-major [col][k]
    __shared__ float w2s[32], b1s[32];
    int tid = threadIdx.x;
    int row0 = blockIdx.x * 64;
    // stage fused tile (float4, coalesced)
    #pragma unroll
    for (int p = 0; p < 4; p++) {
        int i = tid + p * 256;
        int r = i >> 4, e4 = i & 15;
        *(float4*)&fs[r][e4*4] = *(const float4*)&g_fused[(size_t)(row0 + r)*E + e4*4];
    }
    // stage w1 (32x64), w2, b1
    #pragma unroll
    for (int p = 0; p < 2; p++) {
        int i = tid + p * 256;
        int c = i >> 4, e4 = i & 15;
        *(float4*)&w1s[c][e4*4] = *(const float4*)&w1[c*64 + e4*4];
    }
    if (tid < 32) { w2s[tid] = w2[tid]; b1s[tid] = b1[tid]; }
    __syncthreads();
    int col = tid & 31, rgrp = tid >> 5;     // warp = rgrp, lane = col
    ull acc[8];
    #pragma unroll
    for (int r = 0; r < 8; r++) acc[r] = 0;
    #pragma unroll
    for (int k4 = 0; k4 < 16; k4++) {
        ulonglong2 wu = *(const ulonglong2*)&w1s[col][k4*4];
        #pragma unroll
        for (int r = 0; r < 8; r++) {
            ulonglong2 fu = *(const ulonglong2*)&fs[rgrp*8 + r][k4*4];  // broadcast
            acc[r] = ffma2(fu.x, wu.x, acc[r]);
            acc[r] = ffma2(fu.y, wu.y, acc[r]);
        }
    }
    float b2v = b2[0];
    #pragma unroll
    for (int r = 0; r < 8; r++) {
        float lo, hi; upk2(acc[r], lo, hi);
        float h = tanhf(lo + hi + b1s[col]);
        float p = h * w2s[col];
        #pragma unroll
        for (int off = 16; off; off >>= 1)
            p += __shfl_xor_sync(0xffffffffu, p, off);
        if (col == 0) g_scores[row0 + rgrp*8 + r] = p + b2v;
    }
}

// ---------------- softmax over seq + weighted sum -> out[b][e] ----------------
__global__ void pool_out_kernel(float* __restrict__ out) {
    int b = blockIdx.x;
    int tid = threadIdx.x;  // 256
    __shared__ float ws[SEQ];
    __shared__ float red[8];
    __shared__ float s_max, s_sum;
    __shared__ float part[4][64];
    const float* sc = g_scores + (size_t)b * SEQ;
    float m = -1e30f;
    for (int i = tid; i < SEQ; i += 256) m = fmaxf(m, sc[i]);
    #pragma unroll
    for (int off = 16; off; off >>= 1) m = fmaxf(m, __shfl_xor_sync(0xffffffffu, m, off));
    if ((tid & 31) == 0) red[tid >> 5] = m;
    __syncthreads();
    if (tid == 0) {
        float mm = red[0];
        for (int i = 1; i < 8; i++) mm = fmaxf(mm, red[i]);
        s_max = mm;
    }
    __syncthreads();
    float mm = s_max;
    float lsum = 0.f;
    for (int i = tid; i < SEQ; i += 256) {
        float e = __expf(sc[i] - mm);
        ws[i] = e;
        lsum += e;
    }
    #pragma unroll
    for (int off = 16; off; off >>= 1) lsum += __shfl_xor_sync(0xffffffffu, lsum, off);
    __syncthreads();
    if ((tid & 31) == 0) red[tid >> 5] = lsum;
    __syncthreads();
    if (tid == 0) {
        float ss = 0.f;
        for (int i = 0; i < 8; i++) ss += red[i];
        s_sum = ss;
    }
    __syncthreads();
    int e = tid & 63, g = tid >> 6;
    const float* fb = g_fused + (size_t)b * SEQ * E;
    float a0 = 0.f, a1 = 0.f, a2 = 0.f, a3 = 0.f;
    int s0 = g * 256;
    for (int s = s0; s < s0 + 256; s += 4) {
        a0 = fmaf(ws[s],   fb[(size_t)s*E + e],     a0);
        a1 = fmaf(ws[s+1], fb[(size_t)(s+1)*E + e], a1);
        a2 = fmaf(ws[s+2], fb[(size_t)(s+2)*E + e], a2);
        a3 = fmaf(ws[s+3], fb[(size_t)(s+3)*E + e], a3);
    }
    part[g][e] = (a0 + a1) + (a2 + a3);
    __syncthreads();
    if (tid < 64)
        out[b*64 + tid] = (part[0][tid] + part[1][tid] + part[2][tid] + part[3][tid]) / s_sum;
}

// ---------------- launch ----------------
extern "C" void kernel_launch(void* const* d_in, const int* in_sizes, int n_in,
                              void* d_out, int out_size) {
    const float* x        = (const float*)d_in[0];
    const float* proj_w   = (const float*)d_in[1];
    const float* proj_b   = (const float*)d_in[2];
    const float* loc_in_w = (const float*)d_in[3];
    const float* loc_in_b = (const float*)d_in[4];
    const float* loc_out_w= (const float*)d_in[5];
    const float* loc_out_b= (const float*)d_in[6];
    const float* glb_in_w = (const float*)d_in[7];
    const float* glb_in_b = (const float*)d_in[8];
    const float* glb_out_w= (const float*)d_in[9];
    const float* glb_out_b= (const float*)d_in[10];
    const float* fusion_w = (const float*)d_in[11];
    const float* fusion_b = (const float*)d_in[12];
    const float* pool_w1  = (const float*)d_in[13];
    const float* pool_b1  = (const float*)d_in[14];
    const float* pool_w2  = (const float*)d_in[15];
    const float* pool_b2  = (const float*)d_in[16];
    float* out = (float*)d_out;

    combine_proj_kernel<<<16 + ROWS/64, 256>>>(x, proj_w, proj_b,
                                               fusion_w, fusion_b,
                                               loc_out_w, loc_out_b,
                                               glb_out_w, glb_out_b);
    qkv_kernel<<<dim3(ROWS/64, 2), 256>>>(loc_in_w, loc_in_b, glb_in_w, glb_in_b);
    attn_kernel<<<1024, 256>>>();
    fused_kernel<<<ROWS/64, 256>>>();
    pool_score_kernel<<<ROWS/64, 256>>>(pool_w1, pool_b1, pool_w2, pool_b2);
    pool_out_kernel<<<BATCH, 256>>>(out);
}

// round 15
// speedup vs baseline: 1.0244x; 1.0244x over previous
#include <cuda_runtime.h>
#include <math.h>

#define BATCH 16
#define SEQ 1024
#define IN_DIM 310
#define E 64
#define NH 8
#define HD 8
#define ROWS (BATCH*SEQ)          // 16384
#define WIN 5
#define NKEYS 342                 // #{j < 1024 : j%3==0}
#define SCALE 0.35355339059327373f  // 1/sqrt(8)

typedef unsigned long long ull;

// ---------------- f32x2 packed helpers ----------------
__device__ __forceinline__ ull pk2(float lo, float hi) {
    ull r; asm("mov.b64 %0,{%1,%2};" : "=l"(r) : "f"(lo), "f"(hi)); return r;
}
__device__ __forceinline__ void upk2(ull v, float& lo, float& hi) {
    asm("mov.b64 {%0,%1},%2;" : "=f"(lo), "=f"(hi) : "l"(v));
}
__device__ __forceinline__ ull ffma2(ull a, ull b, ull c) {
    ull d; asm("fma.rn.f32x2 %0,%1,%2,%3;" : "=l"(d) : "l"(a), "l"(b), "l"(c)); return d;
}
__device__ __forceinline__ ull fmul2(ull a, ull b) {
    ull d; asm("mul.rn.f32x2 %0,%1,%2;" : "=l"(d) : "l"(a), "l"(b)); return d;
}

// ---------------- scratch ----------------
__device__ float g_xp[ROWS*E];
__device__ float g_q[2][BATCH*NH*SEQ*HD];
__device__ float g_k[2][BATCH*NH*SEQ*HD];
__device__ float g_v[2][BATCH*NH*SEQ*HD];
__device__ float g_o[2][ROWS*E];
__device__ float g_M[2][E*E];     // M_g = fw_g @ out_w_g  (64x64)
__device__ float g_cb[E];         // combined bias
__device__ float g_N[2][32*E];    // N_g = w1 @ M_g  (32x64)
__device__ float g_cb1[32];       // w1 @ cb + b1
__device__ float g_scores[ROWS];  // pooling logits

// ======== split GEMM: 64x64 tile, TWO 128-thread groups, microtile 8x4 each ========
struct HalfSmem {
    float As[16][68];
    float Ws[16][68];
};
struct SplitSmem {
    HalfSmem h[2];
    float part[64][68];
};

__device__ __forceinline__ void gemm64_grp(
    HalfSmem& sm,
    const float* __restrict__ A, int lda, int row0,
    const float* __restrict__ W, int ldw,
    int kb, int ke, int nchunk,
    ull (&acc)[4][4], int t)
{
    int tc = t & 15, tr = t >> 4;   // tr 0..7
    for (int ci = 0; ci < nchunk; ci++) {
        int k0 = kb + ci * 16;
        #pragma unroll
        for (int p = 0; p < 8; p++) {      // A: 64x16
            int i = t + p * 128;
            int kk = i & 15, r = i >> 4;
            int k = k0 + kk;
            sm.As[kk][r] = (k < ke) ? A[(size_t)(row0 + r) * lda + k] : 0.f;
        }
        #pragma unroll
        for (int p = 0; p < 8; p++) {      // W: 64x16
            int i = t + p * 128;
            int kk = i & 15, c = i >> 4;
            int k = k0 + kk;
            sm.Ws[kk][c] = (k < ke) ? W[(size_t)c * ldw + k] : 0.f;
        }
        __syncthreads();
        #pragma unroll
        for (int kk = 0; kk < 16; kk++) {
            ulonglong2 a01 = *(const ulonglong2*)&sm.As[kk][8*tr];
            ulonglong2 a23 = *(const ulonglong2*)&sm.As[kk][8*tr + 4];
            float4 wv = *(const float4*)&sm.Ws[kk][4*tc];
            ull ap[4] = {a01.x, a01.y, a23.x, a23.y};
            ull w2[4] = {pk2(wv.x, wv.x), pk2(wv.y, wv.y), pk2(wv.z, wv.z), pk2(wv.w, wv.w)};
            #pragma unroll
            for (int p = 0; p < 4; p++)
                #pragma unroll
                for (int j = 0; j < 4; j++)
                    acc[p][j] = ffma2(ap[p], w2[j], acc[p][j]);
        }
        __syncthreads();
    }
}

__device__ __forceinline__ void split_reduce_store(
    SplitSmem& sm, ull (&acc)[4][4], int grp, int t,
    const float* __restrict__ bias, float* __restrict__ outbase, int row0)
{
    int tc = t & 15, tr = t >> 4;
    if (grp == 1) {
        #pragma unroll
        for (int p = 0; p < 4; p++) {
            float lo[4], hi[4];
            #pragma unroll
            for (int j = 0; j < 4; j++) upk2(acc[p][j], lo[j], hi[j]);
            int r = 8*tr + 2*p;
            *(float4*)&sm.part[r][4*tc]   = make_float4(lo[0], lo[1], lo[2], lo[3]);
            *(float4*)&sm.part[r+1][4*tc] = make_float4(hi[0], hi[1], hi[2], hi[3]);
        }
    }
    __syncthreads();
    if (grp == 0) {
        float4 bv = *(const float4*)&bias[4*tc];
        #pragma unroll
        for (int p = 0; p < 4; p++) {
            float lo[4], hi[4];
            #pragma unroll
            for (int j = 0; j < 4; j++) upk2(acc[p][j], lo[j], hi[j]);
            int r = 8*tr + 2*p;
            float4 p0 = *(const float4*)&sm.part[r][4*tc];
            float4 p1 = *(const float4*)&sm.part[r+1][4*tc];
            float4 v0 = {lo[0]+p0.x+bv.x, lo[1]+p0.y+bv.y, lo[2]+p0.z+bv.z, lo[3]+p0.w+bv.w};
            float4 v1 = {hi[0]+p1.x+bv.x, hi[1]+p1.y+bv.y, hi[2]+p1.z+bv.z, hi[3]+p1.w+bv.w};
            *(float4*)&outbase[(size_t)(row0 + r)*E + 4*tc] = v0;
            *(float4*)&outbase[(size_t)(row0 + r + 1)*E + 4*tc] = v1;
        }
    }
}

// ---- blocks 0..15: M/cb; blocks 16..23: N/cb1; blocks 24..279: proj ----
__global__ __launch_bounds__(256) void combine_proj_kernel(
    const float* __restrict__ x,
    const float* __restrict__ pw, const float* __restrict__ pb,
    const float* __restrict__ fw, const float* __restrict__ fb,
    const float* __restrict__ low, const float* __restrict__ lob,
    const float* __restrict__ gow, const float* __restrict__ gob,
    const float* __restrict__ w1, const float* __restrict__ b1)
{
    __shared__ SplitSmem sm;
    int tid = threadIdx.x;
    int blk = blockIdx.x;
    if (blk < 16) {
        int idx = blk * 256 + tid;             // 0..4095
        int e = idx >> 6, f = idx & 63;
        float a = 0.f, b = 0.f;
        #pragma unroll 4
        for (int g = 0; g < E; g++) {
            a = fmaf(fw[e*2*E + g],     low[g*E + f], a);
            b = fmaf(fw[e*2*E + E + g], gow[g*E + f], b);
        }
        g_M[0][idx] = a;
        g_M[1][idx] = b;
        if (idx < E) {
            float c = fb[idx];
            for (int g = 0; g < E; g++) {
                c = fmaf(fw[idx*2*E + g], lob[g], c);
                c = fmaf(fw[idx*2*E + E + g], gob[g], c);
            }
            g_cb[idx] = c;
        }
        return;
    }
    if (blk < 24) {
        // N_g = w1 @ M_g via t_g = w1 @ fw_g (4 c-rows per block)
        __shared__ float t0[4][64], t1[4][64];
        int c0 = (blk - 16) * 4;
        int ci = tid >> 6, g = tid & 63;
        {
            float a = 0.f, b = 0.f;
            #pragma unroll 4
            for (int e = 0; e < E; e++) {
                float wv = w1[(c0+ci)*E + e];
                a = fmaf(wv, fw[e*2*E + g], a);
                b = fmaf(wv, fw[e*2*E + E + g], b);
            }
            t0[ci][g] = a;
            t1[ci][g] = b;
        }
        __syncthreads();
        {
            int f = g;
            float a = 0.f, b = 0.f;
            #pragma unroll 4
            for (int gg = 0; gg < E; gg++) {
                a = fmaf(t0[ci][gg], low[gg*E + f], a);
                b = fmaf(t1[ci][gg], gow[gg*E + f], b);
            }
            g_N[0][(c0+ci)*E + f] = a;
            g_N[1][(c0+ci)*E + f] = b;
        }
        if (tid < 4) {
            int c = c0 + tid;
            float s = b1[c];
            for (int e = 0; e < E; e++) s = fmaf(w1[c*E + e], fb[e], s);
            for (int gg = 0; gg < E; gg++) {
                s = fmaf(t0[tid][gg], lob[gg], s);
                s = fmaf(t1[tid][gg], gob[gg], s);
            }
            g_cb1[c] = s;
        }
        return;
    }
    int row0 = (blk - 24) * 64;
    int grp = tid >> 7, t = tid & 127;
    int kb = grp ? 160 : 0;
    int ke = grp ? IN_DIM : 160;
    ull acc[4][4] = {};
    gemm64_grp(sm.h[grp], x, IN_DIM, row0, pw, IN_DIM, kb, ke, 10, acc, t);
    split_reduce_store(sm, acc, grp, t, pb, g_xp, row0);
}

// ---------------- QKV: 64 rows x 192 cols per block, 256 threads ----------------
__global__ __launch_bounds__(256) void qkv_kernel(const float* __restrict__ loc_w,
                           const float* __restrict__ loc_b,
                           const float* __restrict__ glb_w,
                           const float* __restrict__ glb_b) {
    __shared__ float As[16][68];
    __shared__ float Ws[16][196];
    int tid = threadIdx.x;
    int row0 = blockIdx.x * 64;
    int attn = blockIdx.y;
    const float* w    = attn ? glb_w : loc_w;
    const float* bias = attn ? glb_b : loc_b;
    int tc = tid & 15, tr = tid >> 4;
    ull acc[2][12] = {};
    for (int k0 = 0; k0 < E; k0 += 16) {
        #pragma unroll
        for (int p = 0; p < 4; p++) {          // A: 64x16
            int i = tid + p * 256;
            int kk = i & 15, r = i >> 4;
            As[kk][r] = g_xp[(size_t)(row0 + r) * E + k0 + kk];
        }
        #pragma unroll
        for (int p = 0; p < 12; p++) {         // W: 192x16
            int i = tid + p * 256;
            int kk = i & 15, c = i >> 4;
            Ws[kk][c] = w[(size_t)c * E + k0 + kk];
        }
        __syncthreads();
        #pragma unroll
        for (int kk = 0; kk < 16; kk++) {
            ulonglong2 a01 = *(const ulonglong2*)&As[kk][4*tr];
            #pragma unroll
            for (int cg = 0; cg < 3; cg++) {
                float4 wv = *(const float4*)&Ws[kk][64*cg + 4*tc];
                ull w2[4] = {pk2(wv.x, wv.x), pk2(wv.y, wv.y), pk2(wv.z, wv.z), pk2(wv.w, wv.w)};
                #pragma unroll
                for (int j = 0; j < 4; j++) {
                    acc[0][cg*4+j] = ffma2(a01.x, w2[j], acc[0][cg*4+j]);
                    acc[1][cg*4+j] = ffma2(a01.y, w2[j], acc[1][cg*4+j]);
                }
            }
        }
        __syncthreads();
    }
    int c = 4*tc;
    int h = c >> 3, dd = c & 7;
    #pragma unroll
    for (int cg = 0; cg < 3; cg++) {
        float* outp = (cg == 0) ? g_q[attn] : (cg == 1) ? g_k[attn] : g_v[attn];
        float4 bv = *(const float4*)&bias[cg*64 + c];
        #pragma unroll
        for (int p = 0; p < 2; p++) {
            float lo[4], hi[4];
            #pragma unroll
            for (int j = 0; j < 4; j++) upk2(acc[p][cg*4+j], lo[j], hi[j]);
            int row = row0 + 4*tr + 2*p;
            int b0 = row >> 10, s0 = row & 1023;
            int b1i = (row+1) >> 10, s1 = (row+1) & 1023;
            float4 v0 = {lo[0]+bv.x, lo[1]+bv.y, lo[2]+bv.z, lo[3]+bv.w};
            float4 v1 = {hi[0]+bv.x, hi[1]+bv.y, hi[2]+bv.z, hi[3]+bv.w};
            *(float4*)&outp[(((size_t)(b0*NH + h))*SEQ + s0)*HD + dd] = v0;
            *(float4*)&outp[(((size_t)(b1i*NH + h))*SEQ + s1)*HD + dd] = v1;
        }
    }
}

// ---------------- both attentions in one launch ----------------
__global__ __launch_bounds__(256) void attn_kernel() {
    __shared__ union {
        struct { float Ks[NKEYS][8]; float Vs[NKEYS][8]; } sp;
        struct { ull K2[4][272]; ull V2[4][272]; } loc;
    } u;
    int blk = blockIdx.x;
    int tid = threadIdx.x;
    if (blk < 512) {
        // ---- local path ----
        int bh = blk >> 2;
        int chunk0 = (blk & 3) * 256;
        const float* kb = g_k[0] + (size_t)bh * SEQ * HD;
        const float* vb = g_v[0] + (size_t)bh * SEQ * HD;
        for (int i = tid; i < 266*4; i += 256) {
            int dp = i & 3, r = i >> 2;
            int row = chunk0 - 5 + r;
            ull kv = 0, vv = 0;
            if (row >= 0 && row < SEQ) {
                kv = *(const ull*)(kb + (size_t)row*HD + 2*dp);
                vv = *(const ull*)(vb + (size_t)row*HD + 2*dp);
            }
            u.loc.K2[dp][r] = kv;
            u.loc.V2[dp][r] = vv;
        }
        __syncthreads();
        int s = chunk0 + tid;
        const ull* qp = (const ull*)(g_q[0] + ((size_t)bh * SEQ + s) * HD);
        ull q0 = qp[0], q1 = qp[1], q2 = qp[2], q3 = qp[3];
        float l = 0.f;
        ull acc[4] = {0,0,0,0};
        int j0 = s - WIN;
        #pragma unroll
        for (int jj = 0; jj < 2*WIN+1; jj++) {
            int r = tid + jj;
            ull d2 = ffma2(q0, u.loc.K2[0][r],
                     ffma2(q1, u.loc.K2[1][r],
                     ffma2(q2, u.loc.K2[2][r],
                     fmul2(q3, u.loc.K2[3][r]))));
            float dl, dh; upk2(d2, dl, dh);
            unsigned jg = (unsigned)(j0 + jj);
            float p = (jg < SEQ) ? __expf((dl + dh) * SCALE) : 0.f;
            l += p;
            ull pp = pk2(p, p);
            acc[0] = ffma2(pp, u.loc.V2[0][r], acc[0]);
            acc[1] = ffma2(pp, u.loc.V2[1][r], acc[1]);
            acc[2] = ffma2(pp, u.loc.V2[2][r], acc[2]);
            acc[3] = ffma2(pp, u.loc.V2[3][r], acc[3]);
        }
        float inv = 1.f / l;
        float oo[8];
        upk2(acc[0], oo[0], oo[1]); upk2(acc[1], oo[2], oo[3]);
        upk2(acc[2], oo[4], oo[5]); upk2(acc[3], oo[6], oo[7]);
        int b = bh >> 3, h = bh & 7;
        float* op = g_o[0] + ((size_t)(b*SEQ + s))*E + h*HD;
        float4 o0 = {oo[0]*inv, oo[1]*inv, oo[2]*inv, oo[3]*inv};
        float4 o1 = {oo[4]*inv, oo[5]*inv, oo[6]*inv, oo[7]*inv};
        *(float4*)op = o0;
        *(float4*)(op + 4) = o1;
    } else {
        // ---- sparse path ----
        int bb = blk - 512;
        int bh = bb >> 2;
        int s  = (bb & 3) * 256 + tid;
        const float* kb = g_k[1] + (size_t)bh * SEQ * HD;
        const float* vb = g_v[1] + (size_t)bh * SEQ * HD;
        for (int i = tid; i < NKEYS*8; i += 256) {
            int kk = i >> 3, dd = i & 7;
            u.sp.Ks[kk][dd] = kb[kk*24 + dd];
            u.sp.Vs[kk][dd] = vb[kk*24 + dd];
        }
        __syncthreads();
        const ull* qp = (const ull*)(g_q[1] + ((size_t)bh * SEQ + s) * HD);
        ull q0 = qp[0], q1 = qp[1], q2 = qp[2], q3 = qp[3];
        float l = 0.f;
        ull acc[4] = {0,0,0,0};
        #pragma unroll 2
        for (int kk = 0; kk < NKEYS; kk++) {
            const ull* kp = (const ull*)&u.sp.Ks[kk][0];
            ull d2 = ffma2(q0, kp[0], ffma2(q1, kp[1], ffma2(q2, kp[2], fmul2(q3, kp[3]))));
            float dl, dh; upk2(d2, dl, dh);
            float p = __expf((dl + dh) * SCALE);
            l += p;
            ull pp = pk2(p, p);
            const ull* vp = (const ull*)&u.sp.Vs[kk][0];
            acc[0] = ffma2(pp, vp[0], acc[0]);
            acc[1] = ffma2(pp, vp[1], acc[1]);
            acc[2] = ffma2(pp, vp[2], acc[2]);
            acc[3] = ffma2(pp, vp[3], acc[3]);
        }
        if (s % 3) {
            const ull* kp = (const ull*)(kb + (size_t)s * HD);
            ull d2 = ffma2(q0, kp[0], ffma2(q1, kp[1], ffma2(q2, kp[2], fmul2(q3, kp[3]))));
            float dl, dh; upk2(d2, dl, dh);
            float p = __expf((dl + dh) * SCALE);
            l += p;
            ull pp = pk2(p, p);
            const ull* vp = (const ull*)(vb + (size_t)s * HD);
            acc[0] = ffma2(pp, vp[0], acc[0]);
            acc[1] = ffma2(pp, vp[1], acc[1]);
            acc[2] = ffma2(pp, vp[2], acc[2]);
            acc[3] = ffma2(pp, vp[3], acc[3]);
        }
        float inv = 1.f / l;
        float oo[8];
        upk2(acc[0], oo[0], oo[1]); upk2(acc[1], oo[2], oo[3]);
        upk2(acc[2], oo[4], oo[5]); upk2(acc[3], oo[6], oo[7]);
        int b = bh >> 3, h = bh & 7;
        float* op = g_o[1] + ((size_t)(b*SEQ + s))*E + h*HD;
        float4 o0 = {oo[0]*inv, oo[1]*inv, oo[2]*inv, oo[3]*inv};
        float4 o1 = {oo[4]*inv, oo[5]*inv, oo[6]*inv, oo[7]*inv};
        *(float4*)op = o0;
        *(float4*)(op + 4) = o1;
    }
}

// ---------------- score kernel: hidden = o0@N0^T + o1@N1^T (+cb1), tanh, @w2 ----------------
// 64 rows x 32 cols per block; two 128-thread groups (one per source GEMM).
struct ScoreSmem {
    float As[2][16][68];
    float Ws[2][16][36];
    float part[64][36];
    float sp[4][64];
};

__global__ __launch_bounds__(256) void score_kernel(
    const float* __restrict__ w2, const float* __restrict__ b2)
{
    __shared__ ScoreSmem sm;
    int tid = threadIdx.x;
    int row0 = blockIdx.x * 64;
    int grp = tid >> 7, t = tid & 127;
    const float* A = grp ? g_o[1] : g_o[0];
    const float* W = grp ? g_N[1] : g_N[0];
    int tc = t & 7, tr = t >> 3;     // tc 0..7 (4 cols), tr 0..15 (4 rows)
    ull acc[2][4] = {};
    for (int k0 = 0; k0 < E; k0 += 16) {
        #pragma unroll
        for (int p = 0; p < 8; p++) {          // A: 64x16
            int i = t + p * 128;
            int kk = i & 15, r = i >> 4;
            sm.As[grp][kk][r] = A[(size_t)(row0 + r) * E + k0 + kk];
        }
        #pragma unroll
        for (int p = 0; p < 4; p++) {          // W: 32x16
            int i = t + p * 128;
            int kk = i & 15, c = i >> 4;
            sm.Ws[grp][kk][c] = W[(size_t)c * E + k0 + kk];
        }
        __syncthreads();
        #pragma unroll
        for (int kk = 0; kk < 16; kk++) {
            ulonglong2 a01 = *(const ulonglong2*)&sm.As[grp][kk][4*tr];
            float4 wv = *(const float4*)&sm.Ws[grp][kk][4*tc];
            ull w2p[4] = {pk2(wv.x, wv.x), pk2(wv.y, wv.y), pk2(wv.z, wv.z), pk2(wv.w, wv.w)};
            #pragma unroll
            for (int j = 0; j < 4; j++) {
                acc[0][j] = ffma2(a01.x, w2p[j], acc[0][j]);
                acc[1][j] = ffma2(a01.y, w2p[j], acc[1][j]);
            }
        }
        __syncthreads();
    }
    // reduce across groups into part[64][36]
    if (grp == 1) {
        #pragma unroll
        for (int p = 0; p < 2; p++) {
            float lo[4], hi[4];
            #pragma unroll
            for (int j = 0; j < 4; j++) upk2(acc[p][j], lo[j], hi[j]);
            int r = 4*tr + 2*p;
            *(float4*)&sm.part[r][4*tc]   = make_float4(lo[0], lo[1], lo[2], lo[3]);
            *(float4*)&sm.part[r+1][4*tc] = make_float4(hi[0], hi[1], hi[2], hi[3]);
        }
    }
    __syncthreads();
    if (grp == 0) {
        #pragma unroll
        for (int p = 0; p < 2; p++) {
            float lo[4], hi[4];
            #pragma unroll
            for (int j = 0; j < 4; j++) upk2(acc[p][j], lo[j], hi[j]);
            int r = 4*tr + 2*p;
            float4 p0 = *(const float4*)&sm.part[r][4*tc];
            float4 p1 = *(const float4*)&sm.part[r+1][4*tc];
            sm.part[r][4*tc+0] = lo[0]+p0.x; sm.part[r][4*tc+1] = lo[1]+p0.y;
            sm.part[r][4*tc+2] = lo[2]+p0.z; sm.part[r][4*tc+3] = lo[3]+p0.w;
            sm.part[r+1][4*tc+0] = hi[0]+p1.x; sm.part[r+1][4*tc+1] = hi[1]+p1.y;
            sm.part[r+1][4*tc+2] = hi[2]+p1.z; sm.part[r+1][4*tc+3] = hi[3]+p1.w;
        }
    }
    __syncthreads();
    // tanh + w2 dot: thread (r = tid&63, q = tid>>6) handles 8 cols
    {
        int r = tid & 63, q = tid >> 6;
        float s = 0.f;
        #pragma unroll
        for (int c = q*8; c < q*8 + 8; c++) {
            float h = tanhf(sm.part[r][c] + g_cb1[c]);
            s = fmaf(h, w2[c], s);
        }
        sm.sp[q][r] = s;
    }
    __syncthreads();
    if (tid < 64) {
        g_scores[row0 + tid] = sm.sp[0][tid] + sm.sp[1][tid] + sm.sp[2][tid] + sm.sp[3][tid] + b2[0];
    }
}

// ---------------- pool_out: softmax + pooled o0/o1 + tiny final GEMM ----------------
__global__ void pool_out_kernel(float* __restrict__ out) {
    int b = blockIdx.x;
    int tid = threadIdx.x;  // 256
    __shared__ float ws[SEQ];
    __shared__ float red[8];
    __shared__ float s_max, s_sum;
    __shared__ float part0[4][64], part1[4][64];
    __shared__ float pl0[64], pl1[64];
    const float* sc = g_scores + (size_t)b * SEQ;
    float m = -1e30f;
    for (int i = tid; i < SEQ; i += 256) m = fmaxf(m, sc[i]);
    #pragma unroll
    for (int off = 16; off; off >>= 1) m = fmaxf(m, __shfl_xor_sync(0xffffffffu, m, off));
    if ((tid & 31) == 0) red[tid >> 5] = m;
    __syncthreads();
    if (tid == 0) {
        float mm = red[0];
        for (int i = 1; i < 8; i++) mm = fmaxf(mm, red[i]);
        s_max = mm;
    }
    __syncthreads();
    float mm = s_max;
    float lsum = 0.f;
    for (int i = tid; i < SEQ; i += 256) {
        float e = __expf(sc[i] - mm);
        ws[i] = e;
        lsum += e;
    }
    #pragma unroll
    for (int off = 16; off; off >>= 1) lsum += __shfl_xor_sync(0xffffffffu, lsum, off);
    __syncthreads();
    if ((tid & 31) == 0) red[tid >> 5] = lsum;
    __syncthreads();
    if (tid == 0) {
        float ss = 0.f;
        for (int i = 0; i < 8; i++) ss += red[i];
        s_sum = ss;
    }
    __syncthreads();
    int e = tid & 63, g = tid >> 6;
    const float* f0 = g_o[0] + (size_t)b * SEQ * E;
    const float* f1 = g_o[1] + (size_t)b * SEQ * E;
    float a0 = 0.f, a1 = 0.f, b0 = 0.f, b1 = 0.f;
    int s0 = g * 256;
    for (int s = s0; s < s0 + 256; s += 2) {
        a0 = fmaf(ws[s],   f0[(size_t)s*E + e],     a0);
        a1 = fmaf(ws[s+1], f0[(size_t)(s+1)*E + e], a1);
        b0 = fmaf(ws[s],   f1[(size_t)s*E + e],     b0);
        b1 = fmaf(ws[s+1], f1[(size_t)(s+1)*E + e], b1);
    }
    part0[g][e] = a0 + a1;
    part1[g][e] = b0 + b1;
    __syncthreads();
    if (tid < 64) {
        float inv = 1.f / s_sum;
        pl0[tid] = (part0[0][tid] + part0[1][tid] + part0[2][tid] + part0[3][tid]) * inv;
        pl1[tid] = (part1[0][tid] + part1[1][tid] + part1[2][tid] + part1[3][tid]) * inv;
    }
    __syncthreads();
    if (tid < 64) {
        float s = g_cb[tid];
        const float* m0 = &g_M[0][tid*E];
        const float* m1 = &g_M[1][tid*E];
        #pragma unroll 4
        for (int f = 0; f < E; f++) {
            s = fmaf(pl0[f], m0[f], s);
            s = fmaf(pl1[f], m1[f], s);
        }
        out[b*E + tid] = s;
    }
}

// ---------------- launch ----------------
extern "C" void kernel_launch(void* const* d_in, const int* in_sizes, int n_in,
                              void* d_out, int out_size) {
    const float* x        = (const float*)d_in[0];
    const float* proj_w   = (const float*)d_in[1];
    const float* proj_b   = (const float*)d_in[2];
    const float* loc_in_w = (const float*)d_in[3];
    const float* loc_in_b = (const float*)d_in[4];
    const float* loc_out_w= (const float*)d_in[5];
    const float* loc_out_b= (const float*)d_in[6];
    const float* glb_in_w = (const float*)d_in[7];
    const float* glb_in_b = (const float*)d_in[8];
    const float* glb_out_w= (const float*)d_in[9];
    const float* glb_out_b= (const float*)d_in[10];
    const float* fusion_w = (const float*)d_in[11];
    const float* fusion_b = (const float*)d_in[12];
    const float* pool_w1  = (const float*)d_in[13];
    const float* pool_b1  = (const float*)d_in[14];
    const float* pool_w2  = (const float*)d_in[15];
    const float* pool_b2  = (const float*)d_in[16];
    float* out = (float*)d_out;

    combine_proj_kernel<<<24 + ROWS/64, 256>>>(x, proj_w, proj_b,
                                               fusion_w, fusion_b,
                                               loc_out_w, loc_out_b,
                                               glb_out_w, glb_out_b,
                                               pool_w1, pool_b1);
    qkv_kernel<<<dim3(ROWS/64, 2), 256>>>(loc_in_w, loc_in_b, glb_in_w, glb_in_b);
    attn_kernel<<<1024, 256>>>();
    score_kernel<<<ROWS/64, 256>>>(pool_w2, pool_b2);
    pool_out_kernel<<<BATCH, 256>>>(out);
}

// round 16
// speedup vs baseline: 1.1525x; 1.1250x over previous
#include <cuda_runtime.h>
#include <math.h>

#define BATCH 16
#define SEQ 1024
#define IN_DIM 310
#define E 64
#define NH 8
#define HD 8
#define ROWS (BATCH*SEQ)          // 16384
#define WIN 5
#define NKEYS 342                 // #{j < 1024 : j%3==0}
#define SCALE 0.35355339059327373f  // 1/sqrt(8)

typedef unsigned long long ull;

// ---------------- f32x2 packed helpers ----------------
__device__ __forceinline__ ull pk2(float lo, float hi) {
    ull r; asm("mov.b64 %0,{%1,%2};" : "=l"(r) : "f"(lo), "f"(hi)); return r;
}
__device__ __forceinline__ void upk2(ull v, float& lo, float& hi) {
    asm("mov.b64 {%0,%1},%2;" : "=f"(lo), "=f"(hi) : "l"(v));
}
__device__ __forceinline__ ull ffma2(ull a, ull b, ull c) {
    ull d; asm("fma.rn.f32x2 %0,%1,%2,%3;" : "=l"(d) : "l"(a), "l"(b), "l"(c)); return d;
}
__device__ __forceinline__ ull fmul2(ull a, ull b) {
    ull d; asm("mul.rn.f32x2 %0,%1,%2;" : "=l"(d) : "l"(a), "l"(b)); return d;
}

// ---------------- scratch ----------------
__device__ float g_xp[ROWS*E];
__device__ float g_q[2][BATCH*NH*SEQ*HD];
__device__ float g_k[2][BATCH*NH*SEQ*HD];
__device__ float g_v[2][BATCH*NH*SEQ*HD];
__device__ float g_o[2][ROWS*E];
__device__ float g_M[2][E*E];     // M_g = fw_g @ out_w_g  (64x64)
__device__ float g_cb[E];         // combined bias
__device__ float g_N[2][32*E];    // N_g = w1 @ M_g  (32x64)
__device__ float g_cb1[32];       // w1 @ cb + b1
__device__ float g_scores[ROWS];  // pooling logits
__device__ float g_part[2][BATCH][8][64];  // pooled partials
__device__ float g_esum[BATCH][8];         // exp-sum partials

// ======== split GEMM: 64x64 tile, TWO 128-thread groups, microtile 8x4 each ========
struct HalfSmem {
    float As[16][68];
    float Ws[16][68];
};
struct SplitSmem {
    HalfSmem h[2];
    float part[64][68];
};

__device__ __forceinline__ void gemm64_grp(
    HalfSmem& sm,
    const float* __restrict__ A, int lda, int row0,
    const float* __restrict__ W, int ldw,
    int kb, int ke, int nchunk,
    ull (&acc)[4][4], int t)
{
    int tc = t & 15, tr = t >> 4;   // tr 0..7
    for (int ci = 0; ci < nchunk; ci++) {
        int k0 = kb + ci * 16;
        #pragma unroll
        for (int p = 0; p < 8; p++) {      // A: 64x16
            int i = t + p * 128;
            int kk = i & 15, r = i >> 4;
            int k = k0 + kk;
            sm.As[kk][r] = (k < ke) ? A[(size_t)(row0 + r) * lda + k] : 0.f;
        }
        #pragma unroll
        for (int p = 0; p < 8; p++) {      // W: 64x16
            int i = t + p * 128;
            int kk = i & 15, c = i >> 4;
            int k = k0 + kk;
            sm.Ws[kk][c] = (k < ke) ? W[(size_t)c * ldw + k] : 0.f;
        }
        __syncthreads();
        #pragma unroll
        for (int kk = 0; kk < 16; kk++) {
            ulonglong2 a01 = *(const ulonglong2*)&sm.As[kk][8*tr];
            ulonglong2 a23 = *(const ulonglong2*)&sm.As[kk][8*tr + 4];
            float4 wv = *(const float4*)&sm.Ws[kk][4*tc];
            ull ap[4] = {a01.x, a01.y, a23.x, a23.y};
            ull w2[4] = {pk2(wv.x, wv.x), pk2(wv.y, wv.y), pk2(wv.z, wv.z), pk2(wv.w, wv.w)};
            #pragma unroll
            for (int p = 0; p < 4; p++)
                #pragma unroll
                for (int j = 0; j < 4; j++)
                    acc[p][j] = ffma2(ap[p], w2[j], acc[p][j]);
        }
        __syncthreads();
    }
}

__device__ __forceinline__ void split_reduce_store(
    SplitSmem& sm, ull (&acc)[4][4], int grp, int t,
    const float* __restrict__ bias, float* __restrict__ outbase, int row0)
{
    int tc = t & 15, tr = t >> 4;
    if (grp == 1) {
        #pragma unroll
        for (int p = 0; p < 4; p++) {
            float lo[4], hi[4];
            #pragma unroll
            for (int j = 0; j < 4; j++) upk2(acc[p][j], lo[j], hi[j]);
            int r = 8*tr + 2*p;
            *(float4*)&sm.part[r][4*tc]   = make_float4(lo[0], lo[1], lo[2], lo[3]);
            *(float4*)&sm.part[r+1][4*tc] = make_float4(hi[0], hi[1], hi[2], hi[3]);
        }
    }
    __syncthreads();
    if (grp == 0) {
        float4 bv = *(const float4*)&bias[4*tc];
        #pragma unroll
        for (int p = 0; p < 4; p++) {
            float lo[4], hi[4];
            #pragma unroll
            for (int j = 0; j < 4; j++) upk2(acc[p][j], lo[j], hi[j]);
            int r = 8*tr + 2*p;
            float4 p0 = *(const float4*)&sm.part[r][4*tc];
            float4 p1 = *(const float4*)&sm.part[r+1][4*tc];
            float4 v0 = {lo[0]+p0.x+bv.x, lo[1]+p0.y+bv.y, lo[2]+p0.z+bv.z, lo[3]+p0.w+bv.w};
            float4 v1 = {hi[0]+p1.x+bv.x, hi[1]+p1.y+bv.y, hi[2]+p1.z+bv.z, hi[3]+p1.w+bv.w};
            *(float4*)&outbase[(size_t)(row0 + r)*E + 4*tc] = v0;
            *(float4*)&outbase[(size_t)(row0 + r + 1)*E + 4*tc] = v1;
        }
    }
}

// ---- blocks 0..15: M/cb; blocks 16..23: N/cb1; blocks 24..279: proj ----
__global__ __launch_bounds__(256) void combine_proj_kernel(
    const float* __restrict__ x,
    const float* __restrict__ pw, const float* __restrict__ pb,
    const float* __restrict__ fw, const float* __restrict__ fb,
    const float* __restrict__ low, const float* __restrict__ lob,
    const float* __restrict__ gow, const float* __restrict__ gob,
    const float* __restrict__ w1, const float* __restrict__ b1)
{
    __shared__ SplitSmem sm;
    int tid = threadIdx.x;
    int blk = blockIdx.x;
    if (blk < 16) {
        int idx = blk * 256 + tid;             // 0..4095
        int e = idx >> 6, f = idx & 63;
        float a = 0.f, b = 0.f;
        #pragma unroll 4
        for (int g = 0; g < E; g++) {
            a = fmaf(fw[e*2*E + g],     low[g*E + f], a);
            b = fmaf(fw[e*2*E + E + g], gow[g*E + f], b);
        }
        g_M[0][idx] = a;
        g_M[1][idx] = b;
        if (idx < E) {
            float c = fb[idx];
            for (int g = 0; g < E; g++) {
                c = fmaf(fw[idx*2*E + g], lob[g], c);
                c = fmaf(fw[idx*2*E + E + g], gob[g], c);
            }
            g_cb[idx] = c;
        }
        return;
    }
    if (blk < 24) {
        // N_g = w1 @ M_g via t_g = w1 @ fw_g (4 c-rows per block)
        __shared__ float t0[4][64], t1[4][64];
        int c0 = (blk - 16) * 4;
        int ci = tid >> 6, g = tid & 63;
        {
            float a = 0.f, b = 0.f;
            #pragma unroll 4
            for (int e = 0; e < E; e++) {
                float wv = w1[(c0+ci)*E + e];
                a = fmaf(wv, fw[e*2*E + g], a);
                b = fmaf(wv, fw[e*2*E + E + g], b);
            }
            t0[ci][g] = a;
            t1[ci][g] = b;
        }
        __syncthreads();
        {
            int f = g;
            float a = 0.f, b = 0.f;
            #pragma unroll 4
            for (int gg = 0; gg < E; gg++) {
                a = fmaf(t0[ci][gg], low[gg*E + f], a);
                b = fmaf(t1[ci][gg], gow[gg*E + f], b);
            }
            g_N[0][(c0+ci)*E + f] = a;
            g_N[1][(c0+ci)*E + f] = b;
        }
        if (tid < 4) {
            int c = c0 + tid;
            float s = b1[c];
            for (int e = 0; e < E; e++) s = fmaf(w1[c*E + e], fb[e], s);
            for (int gg = 0; gg < E; gg++) {
                s = fmaf(t0[tid][gg], lob[gg], s);
                s = fmaf(t1[tid][gg], gob[gg], s);
            }
            g_cb1[c] = s;
        }
        return;
    }
    int row0 = (blk - 24) * 64;
    int grp = tid >> 7, t = tid & 127;
    int kb = grp ? 160 : 0;
    int ke = grp ? IN_DIM : 160;
    ull acc[4][4] = {};
    gemm64_grp(sm.h[grp], x, IN_DIM, row0, pw, IN_DIM, kb, ke, 10, acc, t);
    split_reduce_store(sm, acc, grp, t, pb, g_xp, row0);
}

// ---------------- QKV: 64 rows x 192 cols per block, 256 threads ----------------
__global__ __launch_bounds__(256) void qkv_kernel(const float* __restrict__ loc_w,
                           const float* __restrict__ loc_b,
                           const float* __restrict__ glb_w,
                           const float* __restrict__ glb_b) {
    __shared__ float As[16][68];
    __shared__ float Ws[16][196];
    int tid = threadIdx.x;
    int row0 = blockIdx.x * 64;
    int attn = blockIdx.y;
    const float* w    = attn ? glb_w : loc_w;
    const float* bias = attn ? glb_b : loc_b;
    int tc = tid & 15, tr = tid >> 4;
    ull acc[2][12] = {};
    for (int k0 = 0; k0 < E; k0 += 16) {
        #pragma unroll
        for (int p = 0; p < 4; p++) {          // A: 64x16
            int i = tid + p * 256;
            int kk = i & 15, r = i >> 4;
            As[kk][r] = g_xp[(size_t)(row0 + r) * E + k0 + kk];
        }
        #pragma unroll
        for (int p = 0; p < 12; p++) {         // W: 192x16
            int i = tid + p * 256;
            int kk = i & 15, c = i >> 4;
            Ws[kk][c] = w[(size_t)c * E + k0 + kk];
        }
        __syncthreads();
        #pragma unroll
        for (int kk = 0; kk < 16; kk++) {
            ulonglong2 a01 = *(const ulonglong2*)&As[kk][4*tr];
            #pragma unroll
            for (int cg = 0; cg < 3; cg++) {
                float4 wv = *(const float4*)&Ws[kk][64*cg + 4*tc];
                ull w2[4] = {pk2(wv.x, wv.x), pk2(wv.y, wv.y), pk2(wv.z, wv.z), pk2(wv.w, wv.w)};
                #pragma unroll
                for (int j = 0; j < 4; j++) {
                    acc[0][cg*4+j] = ffma2(a01.x, w2[j], acc[0][cg*4+j]);
                    acc[1][cg*4+j] = ffma2(a01.y, w2[j], acc[1][cg*4+j]);
                }
            }
        }
        __syncthreads();
    }
    int c = 4*tc;
    int h = c >> 3, dd = c & 7;
    #pragma unroll
    for (int cg = 0; cg < 3; cg++) {
        float* outp = (cg == 0) ? g_q[attn] : (cg == 1) ? g_k[attn] : g_v[attn];
        float4 bv = *(const float4*)&bias[cg*64 + c];
        #pragma unroll
        for (int p = 0; p < 2; p++) {
            float lo[4], hi[4];
            #pragma unroll
            for (int j = 0; j < 4; j++) upk2(acc[p][cg*4+j], lo[j], hi[j]);
            int row = row0 + 4*tr + 2*p;
            int b0 = row >> 10, s0 = row & 1023;
            int b1i = (row+1) >> 10, s1 = (row+1) & 1023;
            float4 v0 = {lo[0]+bv.x, lo[1]+bv.y, lo[2]+bv.z, lo[3]+bv.w};
            float4 v1 = {hi[0]+bv.x, hi[1]+bv.y, hi[2]+bv.z, hi[3]+bv.w};
            *(float4*)&outp[(((size_t)(b0*NH + h))*SEQ + s0)*HD + dd] = v0;
            *(float4*)&outp[(((size_t)(b1i*NH + h))*SEQ + s1)*HD + dd] = v1;
        }
    }
}

// ---------------- both attentions in one launch ----------------
__global__ __launch_bounds__(256) void attn_kernel() {
    __shared__ union {
        struct { float Ks[NKEYS][8]; float Vs[NKEYS][8]; } sp;
        struct { ull K2[4][272]; ull V2[4][272]; } loc;
    } u;
    int blk = blockIdx.x;
    int tid = threadIdx.x;
    if (blk < 512) {
        // ---- local path ----
        int bh = blk >> 2;
        int chunk0 = (blk & 3) * 256;
        const float* kb = g_k[0] + (size_t)bh * SEQ * HD;
        const float* vb = g_v[0] + (size_t)bh * SEQ * HD;
        for (int i = tid; i < 266*4; i += 256) {
            int dp = i & 3, r = i >> 2;
            int row = chunk0 - 5 + r;
            ull kv = 0, vv = 0;
            if (row >= 0 && row < SEQ) {
                kv = *(const ull*)(kb + (size_t)row*HD + 2*dp);
                vv = *(const ull*)(vb + (size_t)row*HD + 2*dp);
            }
            u.loc.K2[dp][r] = kv;
            u.loc.V2[dp][r] = vv;
        }
        __syncthreads();
        int s = chunk0 + tid;
        const ull* qp = (const ull*)(g_q[0] + ((size_t)bh * SEQ + s) * HD);
        ull q0 = qp[0], q1 = qp[1], q2 = qp[2], q3 = qp[3];
        float l = 0.f;
        ull acc[4] = {0,0,0,0};
        int j0 = s - WIN;
        #pragma unroll
        for (int jj = 0; jj < 2*WIN+1; jj++) {
            int r = tid + jj;
            ull d2 = ffma2(q0, u.loc.K2[0][r],
                     ffma2(q1, u.loc.K2[1][r],
                     ffma2(q2, u.loc.K2[2][r],
                     fmul2(q3, u.loc.K2[3][r]))));
            float dl, dh; upk2(d2, dl, dh);
            unsigned jg = (unsigned)(j0 + jj);
            float p = (jg < SEQ) ? __expf((dl + dh) * SCALE) : 0.f;
            l += p;
            ull pp = pk2(p, p);
            acc[0] = ffma2(pp, u.loc.V2[0][r], acc[0]);
            acc[1] = ffma2(pp, u.loc.V2[1][r], acc[1]);
            acc[2] = ffma2(pp, u.loc.V2[2][r], acc[2]);
            acc[3] = ffma2(pp, u.loc.V2[3][r], acc[3]);
        }
        float inv = 1.f / l;
        float oo[8];
        upk2(acc[0], oo[0], oo[1]); upk2(acc[1], oo[2], oo[3]);
        upk2(acc[2], oo[4], oo[5]); upk2(acc[3], oo[6], oo[7]);
        int b = bh >> 3, h = bh & 7;
        float* op = g_o[0] + ((size_t)(b*SEQ + s))*E + h*HD;
        float4 o0 = {oo[0]*inv, oo[1]*inv, oo[2]*inv, oo[3]*inv};
        float4 o1 = {oo[4]*inv, oo[5]*inv, oo[6]*inv, oo[7]*inv};
        *(float4*)op = o0;
        *(float4*)(op + 4) = o1;
    } else {
        // ---- sparse path ----
        int bb = blk - 512;
        int bh = bb >> 2;
        int s  = (bb & 3) * 256 + tid;
        const float* kb = g_k[1] + (size_t)bh * SEQ * HD;
        const float* vb = g_v[1] + (size_t)bh * SEQ * HD;
        for (int i = tid; i < NKEYS*8; i += 256) {
            int kk = i >> 3, dd = i & 7;
            u.sp.Ks[kk][dd] = kb[kk*24 + dd];
            u.sp.Vs[kk][dd] = vb[kk*24 + dd];
        }
        __syncthreads();
        const ull* qp = (const ull*)(g_q[1] + ((size_t)bh * SEQ + s) * HD);
        ull q0 = qp[0], q1 = qp[1], q2 = qp[2], q3 = qp[3];
        float l = 0.f;
        ull acc[4] = {0,0,0,0};
        #pragma unroll 2
        for (int kk = 0; kk < NKEYS; kk++) {
            const ull* kp = (const ull*)&u.sp.Ks[kk][0];
            ull d2 = ffma2(q0, kp[0], ffma2(q1, kp[1], ffma2(q2, kp[2], fmul2(q3, kp[3]))));
            float dl, dh; upk2(d2, dl, dh);
            float p = __expf((dl + dh) * SCALE);
            l += p;
            ull pp = pk2(p, p);
            const ull* vp = (const ull*)&u.sp.Vs[kk][0];
            acc[0] = ffma2(pp, vp[0], acc[0]);
            acc[1] = ffma2(pp, vp[1], acc[1]);
            acc[2] = ffma2(pp, vp[2], acc[2]);
            acc[3] = ffma2(pp, vp[3], acc[3]);
        }
        if (s % 3) {
            const ull* kp = (const ull*)(kb + (size_t)s * HD);
            ull d2 = ffma2(q0, kp[0], ffma2(q1, kp[1], ffma2(q2, kp[2], fmul2(q3, kp[3]))));
            float dl, dh; upk2(d2, dl, dh);
            float p = __expf((dl + dh) * SCALE);
            l += p;
            ull pp = pk2(p, p);
            const ull* vp = (const ull*)(vb + (size_t)s * HD);
            acc[0] = ffma2(pp, vp[0], acc[0]);
            acc[1] = ffma2(pp, vp[1], acc[1]);
            acc[2] = ffma2(pp, vp[2], acc[2]);
            acc[3] = ffma2(pp, vp[3], acc[3]);
        }
        float inv = 1.f / l;
        float oo[8];
        upk2(acc[0], oo[0], oo[1]); upk2(acc[1], oo[2], oo[3]);
        upk2(acc[2], oo[4], oo[5]); upk2(acc[3], oo[6], oo[7]);
        int b = bh >> 3, h = bh & 7;
        float* op = g_o[1] + ((size_t)(b*SEQ + s))*E + h*HD;
        float4 o0 = {oo[0]*inv, oo[1]*inv, oo[2]*inv, oo[3]*inv};
        float4 o1 = {oo[4]*inv, oo[5]*inv, oo[6]*inv, oo[7]*inv};
        *(float4*)op = o0;
        *(float4*)(op + 4) = o1;
    }
}

// ---------------- score kernel: hidden = o0@N0^T + o1@N1^T (+cb1), tanh, @w2 ----------------
struct ScoreSmem {
    float As[2][16][68];
    float Ws[2][16][36];
    float part[64][36];
    float sp[4][64];
};

__global__ __launch_bounds__(256) void score_kernel(
    const float* __restrict__ w2, const float* __restrict__ b2)
{
    __shared__ ScoreSmem sm;
    int tid = threadIdx.x;
    int row0 = blockIdx.x * 64;
    int grp = tid >> 7, t = tid & 127;
    const float* A = grp ? g_o[1] : g_o[0];
    const float* W = grp ? g_N[1] : g_N[0];
    int tc = t & 7, tr = t >> 3;     // tc 0..7 (4 cols), tr 0..15 (4 rows)
    ull acc[2][4] = {};
    for (int k0 = 0; k0 < E; k0 += 16) {
        #pragma unroll
        for (int p = 0; p < 8; p++) {          // A: 64x16
            int i = t + p * 128;
            int kk = i & 15, r = i >> 4;
            sm.As[grp][kk][r] = A[(size_t)(row0 + r) * E + k0 + kk];
        }
        #pragma unroll
        for (int p = 0; p < 4; p++) {          // W: 32x16
            int i = t + p * 128;
            int kk = i & 15, c = i >> 4;
            sm.Ws[grp][kk][c] = W[(size_t)c * E + k0 + kk];
        }
        __syncthreads();
        #pragma unroll
        for (int kk = 0; kk < 16; kk++) {
            ulonglong2 a01 = *(const ulonglong2*)&sm.As[grp][kk][4*tr];
            float4 wv = *(const float4*)&sm.Ws[grp][kk][4*tc];
            ull w2p[4] = {pk2(wv.x, wv.x), pk2(wv.y, wv.y), pk2(wv.z, wv.z), pk2(wv.w, wv.w)};
            #pragma unroll
            for (int j = 0; j < 4; j++) {
                acc[0][j] = ffma2(a01.x, w2p[j], acc[0][j]);
                acc[1][j] = ffma2(a01.y, w2p[j], acc[1][j]);
            }
        }
        __syncthreads();
    }
    if (grp == 1) {
        #pragma unroll
        for (int p = 0; p < 2; p++) {
            float lo[4], hi[4];
            #pragma unroll
            for (int j = 0; j < 4; j++) upk2(acc[p][j], lo[j], hi[j]);
            int r = 4*tr + 2*p;
            *(float4*)&sm.part[r][4*tc]   = make_float4(lo[0], lo[1], lo[2], lo[3]);
            *(float4*)&sm.part[r+1][4*tc] = make_float4(hi[0], hi[1], hi[2], hi[3]);
        }
    }
    __syncthreads();
    if (grp == 0) {
        #pragma unroll
        for (int p = 0; p < 2; p++) {
            float lo[4], hi[4];
            #pragma unroll
            for (int j = 0; j < 4; j++) upk2(acc[p][j], lo[j], hi[j]);
            int r = 4*tr + 2*p;
            float4 p0 = *(const float4*)&sm.part[r][4*tc];
            float4 p1 = *(const float4*)&sm.part[r+1][4*tc];
            sm.part[r][4*tc+0] = lo[0]+p0.x; sm.part[r][4*tc+1] = lo[1]+p0.y;
            sm.part[r][4*tc+2] = lo[2]+p0.z; sm.part[r][4*tc+3] = lo[3]+p0.w;
            sm.part[r+1][4*tc+0] = hi[0]+p1.x; sm.part[r+1][4*tc+1] = hi[1]+p1.y;
            sm.part[r+1][4*tc+2] = hi[2]+p1.z; sm.part[r+1][4*tc+3] = hi[3]+p1.w;
        }
    }
    __syncthreads();
    {
        int r = tid & 63, q = tid >> 6;
        float s = 0.f;
        #pragma unroll
        for (int c = q*8; c < q*8 + 8; c++) {
            float h = tanhf(sm.part[r][c] + g_cb1[c]);
            s = fmaf(h, w2[c], s);
        }
        sm.sp[q][r] = s;
    }
    __syncthreads();
    if (tid < 64) {
        g_scores[row0 + tid] = sm.sp[0][tid] + sm.sp[1][tid] + sm.sp[2][tid] + sm.sp[3][tid] + b2[0];
    }
}

// ---------------- pool_part: per (batch, 128-seq-chunk) weighted partial sums ----------------
// scores are bounded (|s| <~ 6): exp without max subtraction is exact softmax numerator.
__global__ __launch_bounds__(256) void pool_part_kernel() {
    __shared__ float wsm[128];
    __shared__ float p0[4][64], p1[4][64];
    __shared__ float esum_s;
    int blk = blockIdx.x;           // 0..127
    int b = blk >> 3, ch = blk & 7;
    int tid = threadIdx.x;
    int s0 = ch * 128;
    const float* sc = g_scores + (size_t)b * SEQ + s0;
    if (tid < 128) wsm[tid] = __expf(sc[tid]);
    __syncthreads();
    // exp-sum of this chunk (first warp reduces 128 values)
    if (tid < 32) {
        float e = wsm[tid] + wsm[tid+32] + wsm[tid+64] + wsm[tid+96];
        #pragma unroll
        for (int off = 16; off; off >>= 1) e += __shfl_xor_sync(0xffffffffu, e, off);
        if (tid == 0) esum_s = e;
    }
    // weighted partial sums over the 128 rows (4 groups x 32 rows)
    int e = tid & 63, g = tid >> 6;
    const float* f0 = g_o[0] + ((size_t)b * SEQ + s0) * E;
    const float* f1 = g_o[1] + ((size_t)b * SEQ + s0) * E;
    float a0 = 0.f, a1 = 0.f, b0 = 0.f, b1 = 0.f;
    int r0 = g * 32;
    for (int r = r0; r < r0 + 32; r += 2) {
        a0 = fmaf(wsm[r],   f0[(size_t)r*E + e],     a0);
        a1 = fmaf(wsm[r+1], f0[(size_t)(r+1)*E + e], a1);
        b0 = fmaf(wsm[r],   f1[(size_t)r*E + e],     b0);
        b1 = fmaf(wsm[r+1], f1[(size_t)(r+1)*E + e], b1);
    }
    p0[g][e] = a0 + a1;
    p1[g][e] = b0 + b1;
    __syncthreads();
    if (tid < 64) {
        g_part[0][b][ch][tid] = p0[0][tid] + p0[1][tid] + p0[2][tid] + p0[3][tid];
        g_part[1][b][ch][tid] = p1[0][tid] + p1[1][tid] + p1[2][tid] + p1[3][tid];
    }
    if (tid == 0) g_esum[b][ch] = esum_s;
}

// ---------------- pool_final: combine partials + tiny M epilogue ----------------
__global__ void pool_final_kernel(float* __restrict__ out) {
    __shared__ float pl0[64], pl1[64];
    int b = blockIdx.x;
    int tid = threadIdx.x;   // 64
    float es = 0.f;
    #pragma unroll
    for (int c = 0; c < 8; c++) es += g_esum[b][c];
    float inv = 1.f / es;
    float s0 = 0.f, s1 = 0.f;
    #pragma unroll
    for (int c = 0; c < 8; c++) {
        s0 += g_part[0][b][c][tid];
        s1 += g_part[1][b][c][tid];
    }
    pl0[tid] = s0 * inv;
    pl1[tid] = s1 * inv;
    __syncthreads();
    float s = g_cb[tid];
    const float* m0 = &g_M[0][tid*E];
    const float* m1 = &g_M[1][tid*E];
    #pragma unroll 4
    for (int f = 0; f < E; f++) {
        s = fmaf(pl0[f], m0[f], s);
        s = fmaf(pl1[f], m1[f], s);
    }
    out[b*E + tid] = s;
}

// ---------------- launch ----------------
extern "C" void kernel_launch(void* const* d_in, const int* in_sizes, int n_in,
                              void* d_out, int out_size) {
    const float* x        = (const float*)d_in[0];
    const float* proj_w   = (const float*)d_in[1];
    const float* proj_b   = (const float*)d_in[2];
    const float* loc_in_w = (const float*)d_in[3];
    const float* loc_in_b = (const float*)d_in[4];
    const float* loc_out_w= (const float*)d_in[5];
    const float* loc_out_b= (const float*)d_in[6];
    const float* glb_in_w = (const float*)d_in[7];
    const float* glb_in_b = (const float*)d_in[8];
    const float* glb_out_w= (const float*)d_in[9];
    const float* glb_out_b= (const float*)d_in[10];
    const float* fusion_w = (const float*)d_in[11];
    const float* fusion_b = (const float*)d_in[12];
    const float* pool_w1  = (const float*)d_in[13];
    const float* pool_b1  = (const float*)d_in[14];
    const float* pool_w2  = (const float*)d_in[15];
    const float* pool_b2  = (const float*)d_in[16];
    float* out = (float*)d_out;

    combine_proj_kernel<<<24 + ROWS/64, 256>>>(x, proj_w, proj_b,
                                               fusion_w, fusion_b,
                                               loc_out_w, loc_out_b,
                                               glb_out_w, glb_out_b,
                                               pool_w1, pool_b1);
    qkv_kernel<<<dim3(ROWS/64, 2), 256>>>(loc_in_w, loc_in_b, glb_in_w, glb_in_b);
    attn_kernel<<<1024, 256>>>();
    score_kernel<<<ROWS/64, 256>>>(pool_w2, pool_b2);
    pool_part_kernel<<<128, 256>>>();
    pool_final_kernel<<<BATCH, 64>>>(out);
}